// round 1
// baseline (speedup 1.0000x reference)
#include <cuda_runtime.h>
#include <math.h>

// Problem constants
#define DIMC   768
#define HEADSC 12
#define HDC    64
#define BC     2
#define NC     1024
#define MLPC   3072
#define ROWS   (BC * NC)            // 2048
#define NN     (NC * NC)            // 1048576 = 1<<20
#define SCALEC 0.125f               // 64^-0.5

// ---------------- scratch (no allocations allowed) ----------------
__device__ float g_h  [ROWS * DIMC];            // ln1 out
__device__ float g_qkv[ROWS * 3 * DIMC];        // qkv gemm out [B,N,3*DIM]
__device__ float g_qk [(size_t)BC * HEADSC * NN]; // raw scores, then attn (in place)
__device__ float g_av [ROWS * DIMC];            // attn @ v, head-merged layout
__device__ float g_x1 [ROWS * DIMC];            // x + proj
__device__ float g_h2 [ROWS * DIMC];            // ln2 out
__device__ float g_fc1[ROWS * MLPC];            // gelu(fc1)

// ---------------- layernorm: one block per row, 256 threads ----------------
__global__ void ln_kernel(const float* __restrict__ x, const float* __restrict__ g,
                          const float* __restrict__ b, float* __restrict__ y) {
    int row = blockIdx.x;
    const float* xr = x + (size_t)row * DIMC;
    float*       yr = y + (size_t)row * DIMC;
    float v[3];
    float s = 0.f, s2 = 0.f;
#pragma unroll
    for (int i = 0; i < 3; i++) {
        v[i] = xr[threadIdx.x + 256 * i];
        s += v[i]; s2 += v[i] * v[i];
    }
    __shared__ float sh[16];
#pragma unroll
    for (int o = 16; o; o >>= 1) {
        s  += __shfl_xor_sync(~0u, s,  o);
        s2 += __shfl_xor_sync(~0u, s2, o);
    }
    int w = threadIdx.x >> 5;
    if ((threadIdx.x & 31) == 0) { sh[w] = s; sh[8 + w] = s2; }
    __syncthreads();
    if (threadIdx.x < 32) {
        s  = threadIdx.x < 8 ? sh[threadIdx.x]     : 0.f;
        s2 = threadIdx.x < 8 ? sh[8 + threadIdx.x] : 0.f;
#pragma unroll
        for (int o = 4; o; o >>= 1) {
            s  += __shfl_xor_sync(~0u, s,  o);
            s2 += __shfl_xor_sync(~0u, s2, o);
        }
        if (threadIdx.x == 0) { sh[0] = s; sh[1] = s2; }
    }
    __syncthreads();
    float mean = sh[0] * (1.f / DIMC);
    float var  = sh[1] * (1.f / DIMC) - mean * mean;
    float rstd = rsqrtf(var + 1e-5f);
#pragma unroll
    for (int i = 0; i < 3; i++) {
        int c = threadIdx.x + 256 * i;
        yr[c] = (v[i] - mean) * rstd * g[c] + b[c];
    }
}

// ---------------- softmax over last dim (row = b*H*N + h*N + n) ----------------
__global__ void softmax_kernel(const float* __restrict__ qk, float* __restrict__ am) {
    size_t base = (size_t)blockIdx.x * NC;
    float v[4];
    float m = -1e30f;
#pragma unroll
    for (int i = 0; i < 4; i++) {
        v[i] = qk[base + threadIdx.x + 256 * i] * SCALEC;
        m = fmaxf(m, v[i]);
    }
    __shared__ float sh[8];
#pragma unroll
    for (int o = 16; o; o >>= 1) m = fmaxf(m, __shfl_xor_sync(~0u, m, o));
    if ((threadIdx.x & 31) == 0) sh[threadIdx.x >> 5] = m;
    __syncthreads();
    if (threadIdx.x < 32) {
        m = threadIdx.x < 8 ? sh[threadIdx.x] : -1e30f;
#pragma unroll
        for (int o = 4; o; o >>= 1) m = fmaxf(m, __shfl_xor_sync(~0u, m, o));
        if (threadIdx.x == 0) sh[0] = m;
    }
    __syncthreads();
    m = sh[0];
    __syncthreads();          // protect sh reuse
    float s = 0.f;
#pragma unroll
    for (int i = 0; i < 4; i++) { v[i] = __expf(v[i] - m); s += v[i]; }
#pragma unroll
    for (int o = 16; o; o >>= 1) s += __shfl_xor_sync(~0u, s, o);
    if ((threadIdx.x & 31) == 0) sh[threadIdx.x >> 5] = s;
    __syncthreads();
    if (threadIdx.x < 32) {
        s = threadIdx.x < 8 ? sh[threadIdx.x] : 0.f;
#pragma unroll
        for (int o = 4; o; o >>= 1) s += __shfl_xor_sync(~0u, s, o);
        if (threadIdx.x == 0) sh[0] = s;
    }
    __syncthreads();
    float inv = 1.f / sh[0];
#pragma unroll
    for (int i = 0; i < 4; i++)
        am[base + threadIdx.x + 256 * i] = v[i] * inv;
}

// -------- uncertainty = sigmoid(conv over heads of raw qk) ; attn = am + u*r (in place) -----
__global__ void uncert_kernel(const float* __restrict__ r, const float* __restrict__ cw,
                              const float* __restrict__ cb, float* __restrict__ qk,
                              const float* __restrict__ am, float* __restrict__ unc) {
    __shared__ float scw[HEADSC * HEADSC];
    __shared__ float scb[HEADSC];
    if (threadIdx.x < HEADSC * HEADSC) scw[threadIdx.x] = cw[threadIdx.x];
    if (threadIdx.x < HEADSC)          scb[threadIdx.x] = cb[threadIdx.x];
    __syncthreads();
    size_t idx = (size_t)blockIdx.x * 256 + threadIdx.x;   // < B*N*N
    int    bb  = (int)(idx >> 20);
    size_t nm  = idx & (size_t)(NN - 1);
    size_t base = ((size_t)bb * HEADSC << 20) + nm;
    float s[HEADSC];
#pragma unroll
    for (int h = 0; h < HEADSC; h++) s[h] = qk[base + ((size_t)h << 20)];
#pragma unroll
    for (int g = 0; g < HEADSC; g++) {
        float acc = scb[g];
#pragma unroll
        for (int h = 0; h < HEADSC; h++) acc += scw[g * HEADSC + h] * s[h];
        float u = 1.f / (1.f + __expf(-acc));
        size_t o = base + ((size_t)g << 20);
        unc[o] = u;
        qk[o]  = am[o] + u * r[o];
    }
}

// ---------------- tiled GEMM, C = A * B^T, 64x64x16, 256 thr, 4x4/thread ----------------
// epi: 0 none, 1 +bias, 2 +bias+gelu, 3 +bias+residual
// batching: z -> (zb = z/Hdiv, zh = z%Hdiv); ptr += zb*s?b + zh*s?h
__global__ void gemm_nt(const float* __restrict__ A, const float* __restrict__ B,
                        float* __restrict__ C, const float* __restrict__ bias,
                        const float* __restrict__ res,
                        int K, int lda, int ldb, int ldc,
                        long sAb, long sAh, long sBb, long sBh, long sCb, long sCh,
                        int Hdiv, int epi) {
    int z = blockIdx.z;
    int zb = z / Hdiv, zh = z % Hdiv;
    A += zb * sAb + zh * sAh;
    B += zb * sBb + zh * sBh;
    C += zb * sCb + zh * sCh;
    if (epi == 3) res += zb * sCb + zh * sCh;

    __shared__ float As[16][64];
    __shared__ float Bs[16][64];
    int m0 = blockIdx.y * 64, n0 = blockIdx.x * 64;
    int t  = threadIdx.x;
    int tx = t & 15, ty = t >> 4;
    int lr = t >> 2;          // 0..63
    int lk = (t & 3) * 4;     // 0,4,8,12
    float acc[4][4] = {};

    for (int k0 = 0; k0 < K; k0 += 16) {
        float4 a4 = *(const float4*)(A + (size_t)(m0 + lr) * lda + k0 + lk);
        float4 b4 = *(const float4*)(B + (size_t)(n0 + lr) * ldb + k0 + lk);
        __syncthreads();
        As[lk + 0][lr] = a4.x; As[lk + 1][lr] = a4.y; As[lk + 2][lr] = a4.z; As[lk + 3][lr] = a4.w;
        Bs[lk + 0][lr] = b4.x; Bs[lk + 1][lr] = b4.y; Bs[lk + 2][lr] = b4.z; Bs[lk + 3][lr] = b4.w;
        __syncthreads();
#pragma unroll
        for (int k = 0; k < 16; k++) {
            float a[4], bv[4];
#pragma unroll
            for (int i = 0; i < 4; i++) a[i]  = As[k][ty + 16 * i];
#pragma unroll
            for (int j = 0; j < 4; j++) bv[j] = Bs[k][tx + 16 * j];
#pragma unroll
            for (int i = 0; i < 4; i++)
#pragma unroll
                for (int j = 0; j < 4; j++) acc[i][j] += a[i] * bv[j];
        }
    }
#pragma unroll
    for (int i = 0; i < 4; i++) {
        int row = m0 + ty + 16 * i;
#pragma unroll
        for (int j = 0; j < 4; j++) {
            int col = n0 + tx + 16 * j;
            float v = acc[i][j];
            if (epi >= 1) v += bias[col];
            if (epi == 2) {
                float u = v;
                v = 0.5f * u * (1.f + tanhf(0.7978845608f * (u + 0.044715f * u * u * u)));
            }
            if (epi == 3) v += res[(size_t)row * ldc + col];
            C[(size_t)row * ldc + col] = v;
        }
    }
}

// ---------------- tiled GEMM, C = A * B (NN), for attn @ V ----------------
__global__ void gemm_nn(const float* __restrict__ A, const float* __restrict__ B,
                        float* __restrict__ C,
                        int K, int lda, int ldb, int ldc,
                        long sAb, long sAh, long sBb, long sBh, long sCb, long sCh,
                        int Hdiv) {
    int z = blockIdx.z;
    int zb = z / Hdiv, zh = z % Hdiv;
    A += zb * sAb + zh * sAh;
    B += zb * sBb + zh * sBh;
    C += zb * sCb + zh * sCh;

    __shared__ float As[16][64];
    __shared__ float Bs[16][64];
    int m0 = blockIdx.y * 64, n0 = blockIdx.x * 64;
    int t  = threadIdx.x;
    int tx = t & 15, ty = t >> 4;
    int lr = t >> 2;          // A tile row 0..63
    int lk = (t & 3) * 4;
    int brow = t >> 4;        // B tile row 0..15
    int bcol = (t & 15) * 4;  // B tile col 0,4,..,60
    float acc[4][4] = {};

    for (int k0 = 0; k0 < K; k0 += 16) {
        float4 a4 = *(const float4*)(A + (size_t)(m0 + lr) * lda + k0 + lk);
        float4 b4 = *(const float4*)(B + (size_t)(k0 + brow) * ldb + n0 + bcol);
        __syncthreads();
        As[lk + 0][lr] = a4.x; As[lk + 1][lr] = a4.y; As[lk + 2][lr] = a4.z; As[lk + 3][lr] = a4.w;
        *(float4*)&Bs[brow][bcol] = b4;
        __syncthreads();
#pragma unroll
        for (int k = 0; k < 16; k++) {
            float a[4], bv[4];
#pragma unroll
            for (int i = 0; i < 4; i++) a[i]  = As[k][ty + 16 * i];
#pragma unroll
            for (int j = 0; j < 4; j++) bv[j] = Bs[k][tx + 16 * j];
#pragma unroll
            for (int i = 0; i < 4; i++)
#pragma unroll
                for (int j = 0; j < 4; j++) acc[i][j] += a[i] * bv[j];
        }
    }
#pragma unroll
    for (int i = 0; i < 4; i++) {
        int row = m0 + ty + 16 * i;
#pragma unroll
        for (int j = 0; j < 4; j++) {
            int col = n0 + tx + 16 * j;
            C[(size_t)row * ldc + col] = acc[i][j];
        }
    }
}

// ---------------- host launch ----------------
extern "C" void kernel_launch(void* const* d_in, const int* in_sizes, int n_in,
                              void* d_out, int out_size) {
    const float* x      = (const float*)d_in[0];
    const float* r      = (const float*)d_in[1];
    const float* ln1_g  = (const float*)d_in[2];
    const float* ln1_b  = (const float*)d_in[3];
    const float* qkv_w  = (const float*)d_in[4];
    const float* qkv_b  = (const float*)d_in[5];
    const float* conv_w = (const float*)d_in[6];
    const float* conv_b = (const float*)d_in[7];
    const float* proj_w = (const float*)d_in[8];
    const float* proj_b = (const float*)d_in[9];
    const float* ln2_g  = (const float*)d_in[10];
    const float* ln2_b  = (const float*)d_in[11];
    const float* fc1_w  = (const float*)d_in[12];
    const float* fc1_b  = (const float*)d_in[13];
    const float* fc2_w  = (const float*)d_in[14];
    const float* fc2_b  = (const float*)d_in[15];

    float* out    = (float*)d_out;
    float* out_x  = out;                                   // [B,N,DIM]
    float* out_am = out + (size_t)ROWS * DIMC;             // [B,H,N,N]
    float* out_un = out_am + (size_t)BC * HEADSC * NN;     // [B,H,N,N]

    float *h_, *qkv_, *qk_, *av_, *x1_, *h2_, *fc1_;
    cudaGetSymbolAddress((void**)&h_,   g_h);
    cudaGetSymbolAddress((void**)&qkv_, g_qkv);
    cudaGetSymbolAddress((void**)&qk_,  g_qk);
    cudaGetSymbolAddress((void**)&av_,  g_av);
    cudaGetSymbolAddress((void**)&x1_,  g_x1);
    cudaGetSymbolAddress((void**)&h2_,  g_h2);
    cudaGetSymbolAddress((void**)&fc1_, g_fc1);

    // 1. ln1
    ln_kernel<<<ROWS, 256>>>(x, ln1_g, ln1_b, h_);

    // 2. qkv = h @ qkv_w^T + qkv_b   [2048, 2304]
    gemm_nt<<<dim3(3 * DIMC / 64, ROWS / 64, 1), 256>>>(
        h_, qkv_w, qkv_, qkv_b, nullptr,
        DIMC, DIMC, DIMC, 3 * DIMC,
        0, 0, 0, 0, 0, 0, 1, /*epi=*/1);

    // 3. qk[b,h] = Q[b,h] @ K[b,h]^T   (24 batches of 1024x1024x64, raw scores)
    gemm_nt<<<dim3(NC / 64, NC / 64, BC * HEADSC), 256>>>(
        qkv_, qkv_ + DIMC, qk_, nullptr, nullptr,
        HDC, 3 * DIMC, 3 * DIMC, NC,
        (long)NC * 3 * DIMC, HDC,
        (long)NC * 3 * DIMC, HDC,
        (long)HEADSC * NN, (long)NN,
        HEADSC, /*epi=*/0);

    // 4. attn_mean = softmax(qk * SCALE)
    softmax_kernel<<<BC * HEADSC * NC, 256>>>(qk_, out_am);

    // 5. uncertainty + attn (in place over qk_)
    uncert_kernel<<<(BC * NN) / 256, 256>>>(r, conv_w, conv_b, qk_, out_am, out_un);

    // 6. av[b,h] = attn[b,h] @ V[b,h]   (24 batches of 1024x64x1024), head-merged out
    gemm_nn<<<dim3(1, NC / 64, BC * HEADSC), 256>>>(
        qk_, qkv_ + 2 * DIMC, av_,
        NC, NC, 3 * DIMC, DIMC,
        (long)HEADSC * NN, (long)NN,
        (long)NC * 3 * DIMC, HDC,
        (long)NC * DIMC, HDC,
        HEADSC);

    // 7. x1 = x + av @ proj_w^T + proj_b
    gemm_nt<<<dim3(DIMC / 64, ROWS / 64, 1), 256>>>(
        av_, proj_w, x1_, proj_b, x,
        DIMC, DIMC, DIMC, DIMC,
        0, 0, 0, 0, 0, 0, 1, /*epi=*/3);

    // 8. ln2
    ln_kernel<<<ROWS, 256>>>(x1_, ln2_g, ln2_b, h2_);

    // 9. fc1 = gelu(h2 @ fc1_w^T + fc1_b)
    gemm_nt<<<dim3(MLPC / 64, ROWS / 64, 1), 256>>>(
        h2_, fc1_w, fc1_, fc1_b, nullptr,
        DIMC, DIMC, DIMC, MLPC,
        0, 0, 0, 0, 0, 0, 1, /*epi=*/2);

    // 10. out_x = x1 + fc1 @ fc2_w^T + fc2_b
    gemm_nt<<<dim3(DIMC / 64, ROWS / 64, 1), 256>>>(
        fc1_, fc2_w, out_x, fc2_b, x1_,
        MLPC, MLPC, MLPC, DIMC,
        0, 0, 0, 0, 0, 0, 1, /*epi=*/3);
}

// round 2
// speedup vs baseline: 1.9148x; 1.9148x over previous
#include <cuda_runtime.h>
#include <mma.h>
#include <math.h>

using namespace nvcuda;

// Problem constants
#define DIMC   768
#define HEADSC 12
#define HDC    64
#define BC     2
#define NC     1024
#define MLPC   3072
#define ROWS   (BC * NC)            // 2048
#define NN     (NC * NC)            // 1<<20
#define SCALEC 0.125f

// ---------------- scratch ----------------
__device__ float g_h  [ROWS * DIMC];
__device__ float g_qkv[ROWS * 3 * DIMC];
__device__ float g_qk [(size_t)BC * HEADSC * NN];
__device__ float g_av [ROWS * DIMC];
__device__ float g_x1 [ROWS * DIMC];
__device__ float g_h2 [ROWS * DIMC];
__device__ float g_fc1[ROWS * MLPC];

// ---------------- layernorm ----------------
__global__ void ln_kernel(const float* __restrict__ x, const float* __restrict__ g,
                          const float* __restrict__ b, float* __restrict__ y) {
    int row = blockIdx.x;
    const float* xr = x + (size_t)row * DIMC;
    float*       yr = y + (size_t)row * DIMC;
    float v[3];
    float s = 0.f, s2 = 0.f;
#pragma unroll
    for (int i = 0; i < 3; i++) {
        v[i] = xr[threadIdx.x + 256 * i];
        s += v[i]; s2 += v[i] * v[i];
    }
    __shared__ float sh[16];
#pragma unroll
    for (int o = 16; o; o >>= 1) {
        s  += __shfl_xor_sync(~0u, s,  o);
        s2 += __shfl_xor_sync(~0u, s2, o);
    }
    int w = threadIdx.x >> 5;
    if ((threadIdx.x & 31) == 0) { sh[w] = s; sh[8 + w] = s2; }
    __syncthreads();
    if (threadIdx.x < 32) {
        s  = threadIdx.x < 8 ? sh[threadIdx.x]     : 0.f;
        s2 = threadIdx.x < 8 ? sh[8 + threadIdx.x] : 0.f;
#pragma unroll
        for (int o = 4; o; o >>= 1) {
            s  += __shfl_xor_sync(~0u, s,  o);
            s2 += __shfl_xor_sync(~0u, s2, o);
        }
        if (threadIdx.x == 0) { sh[0] = s; sh[1] = s2; }
    }
    __syncthreads();
    float mean = sh[0] * (1.f / DIMC);
    float var  = sh[1] * (1.f / DIMC) - mean * mean;
    float rstd = rsqrtf(var + 1e-5f);
#pragma unroll
    for (int i = 0; i < 3; i++) {
        int c = threadIdx.x + 256 * i;
        yr[c] = (v[i] - mean) * rstd * g[c] + b[c];
    }
}

// ---------------- softmax ----------------
__global__ void softmax_kernel(const float* __restrict__ qk, float* __restrict__ am) {
    size_t base = (size_t)blockIdx.x * NC;
    float v[4];
    float m = -1e30f;
#pragma unroll
    for (int i = 0; i < 4; i++) {
        v[i] = qk[base + threadIdx.x + 256 * i] * SCALEC;
        m = fmaxf(m, v[i]);
    }
    __shared__ float sh[8];
#pragma unroll
    for (int o = 16; o; o >>= 1) m = fmaxf(m, __shfl_xor_sync(~0u, m, o));
    if ((threadIdx.x & 31) == 0) sh[threadIdx.x >> 5] = m;
    __syncthreads();
    if (threadIdx.x < 32) {
        m = threadIdx.x < 8 ? sh[threadIdx.x] : -1e30f;
#pragma unroll
        for (int o = 4; o; o >>= 1) m = fmaxf(m, __shfl_xor_sync(~0u, m, o));
        if (threadIdx.x == 0) sh[0] = m;
    }
    __syncthreads();
    m = sh[0];
    __syncthreads();
    float s = 0.f;
#pragma unroll
    for (int i = 0; i < 4; i++) { v[i] = __expf(v[i] - m); s += v[i]; }
#pragma unroll
    for (int o = 16; o; o >>= 1) s += __shfl_xor_sync(~0u, s, o);
    if ((threadIdx.x & 31) == 0) sh[threadIdx.x >> 5] = s;
    __syncthreads();
    if (threadIdx.x < 32) {
        s = threadIdx.x < 8 ? sh[threadIdx.x] : 0.f;
#pragma unroll
        for (int o = 4; o; o >>= 1) s += __shfl_xor_sync(~0u, s, o);
        if (threadIdx.x == 0) sh[0] = s;
    }
    __syncthreads();
    float inv = 1.f / sh[0];
#pragma unroll
    for (int i = 0; i < 4; i++)
        am[base + threadIdx.x + 256 * i] = v[i] * inv;
}

// -------- uncertainty + attn (in place) --------
__global__ void uncert_kernel(const float* __restrict__ r, const float* __restrict__ cw,
                              const float* __restrict__ cb, float* __restrict__ qk,
                              const float* __restrict__ am, float* __restrict__ unc) {
    __shared__ float scw[HEADSC * HEADSC];
    __shared__ float scb[HEADSC];
    if (threadIdx.x < HEADSC * HEADSC) scw[threadIdx.x] = cw[threadIdx.x];
    if (threadIdx.x < HEADSC)          scb[threadIdx.x] = cb[threadIdx.x];
    __syncthreads();
    size_t idx = (size_t)blockIdx.x * 256 + threadIdx.x;
    int    bb  = (int)(idx >> 20);
    size_t nm  = idx & (size_t)(NN - 1);
    size_t base = ((size_t)bb * HEADSC << 20) + nm;
    float s[HEADSC];
#pragma unroll
    for (int h = 0; h < HEADSC; h++) s[h] = qk[base + ((size_t)h << 20)];
#pragma unroll
    for (int g = 0; g < HEADSC; g++) {
        float acc = scb[g];
#pragma unroll
        for (int h = 0; h < HEADSC; h++) acc += scw[g * HEADSC + h] * s[h];
        float u = 1.f / (1.f + __expf(-acc));
        size_t o = base + ((size_t)g << 20);
        unc[o] = u;
        qk[o]  = am[o] + u * r[o];
    }
}

// ---------------- tf32 tensor-core GEMM ----------------
// C[M,N] = A[M,K] * op(B), op = B^T (BLAY=0, B is [N,K]) or B (BLAY=1, B is [K,N])
// 128 x BN tiles, BK=32, 8 warps (4 along M x 2 along N), wmma m16n16k8 tf32.
// epi: 0 none, 1 +bias, 2 +bias+gelu, 3 +bias+residual
#define BKC 32
#define LDA_S 36           // BK + 4

__device__ __forceinline__ void cpa16(float* dst, const float* src) {
    unsigned s = (unsigned)__cvta_generic_to_shared(dst);
    asm volatile("cp.async.cg.shared.global [%0], [%1], 16;" :: "r"(s), "l"(src));
}

template<int BN, int BLAY, int EPI>
__global__ __launch_bounds__(256)
void gemm_tc(const float* __restrict__ A, const float* __restrict__ B,
             float* __restrict__ C, const float* __restrict__ bias,
             const float* __restrict__ res,
             int K, int lda, int ldb, int ldc,
             long sAb, long sAh, long sBb, long sBh, long sCb, long sCh,
             int Hdiv) {
    constexpr int BM  = 128;
    constexpr int WN  = BN / 2;          // warp tile N
    constexpr int NFR = WN / 16;         // b/acc frags along N
    constexpr int ASZ = BM * LDA_S;                       // floats
    constexpr int BSZ = (BLAY == 0) ? BN * LDA_S : BKC * (BN + 4);
    constexpr int LDB_S = (BLAY == 0) ? LDA_S : (BN + 4);

    extern __shared__ float smem[];
    float* As[2] = { smem,            smem + ASZ + BSZ };
    float* Bs[2] = { smem + ASZ,      smem + 2 * ASZ + BSZ };

    int z  = blockIdx.z;
    int zb = z / Hdiv, zh = z % Hdiv;
    A += zb * sAb + zh * sAh;
    B += zb * sBb + zh * sBh;
    C += zb * sCb + zh * sCh;
    if (EPI == 3) res += zb * sCb + zh * sCh;

    int m0 = blockIdx.y * BM, n0 = blockIdx.x * BN;
    int t  = threadIdx.x;
    int wid = t >> 5;
    int wm = wid & 3;        // 0..3
    int wn = wid >> 2;       // 0..1

    wmma::fragment<wmma::accumulator, 16, 16, 8, float> acc[2][NFR];
#pragma unroll
    for (int i = 0; i < 2; i++)
#pragma unroll
        for (int j = 0; j < NFR; j++) wmma::fill_fragment(acc[i][j], 0.f);

    const int stages = K / BKC;

    auto load_tiles = [&](int k0, int st) {
        // A tile: BM x BK
#pragma unroll
        for (int i = 0; i < BM * BKC / 4 / 256; i++) {
            int f4  = t + i * 256;
            int row = f4 >> 3;               // / (BK/4)
            int c4  = (f4 & 7) * 4;
            cpa16(As[st] + row * LDA_S + c4,
                  A + (size_t)(m0 + row) * lda + k0 + c4);
        }
        if (BLAY == 0) {
            // B tile: BN rows x BK (from [N,K])
#pragma unroll
            for (int i = 0; i < BN * BKC / 4 / 256; i++) {
                int f4  = t + i * 256;
                int row = f4 >> 3;
                int c4  = (f4 & 7) * 4;
                cpa16(Bs[st] + row * LDA_S + c4,
                      B + (size_t)(n0 + row) * ldb + k0 + c4);
            }
        } else {
            // B tile: BK rows x BN (from [K,N])
#pragma unroll
            for (int i = 0; i < BKC * BN / 4 / 256; i++) {
                int f4  = t + i * 256;
                int row = f4 / (BN / 4);
                int c4  = (f4 % (BN / 4)) * 4;
                cpa16(Bs[st] + row * LDB_S + c4,
                      B + (size_t)(k0 + row) * ldb + n0 + c4);
            }
        }
        asm volatile("cp.async.commit_group;" ::: "memory");
    };

    load_tiles(0, 0);

    for (int it = 0; it < stages; ++it) {
        int cur = it & 1;
        if (it + 1 < stages) {
            load_tiles((it + 1) * BKC, cur ^ 1);
            asm volatile("cp.async.wait_group 1;" ::: "memory");
        } else {
            asm volatile("cp.async.wait_group 0;" ::: "memory");
        }
        __syncthreads();

        const float* as = As[cur];
        const float* bs = Bs[cur];
#pragma unroll
        for (int kk = 0; kk < BKC; kk += 8) {
            wmma::fragment<wmma::matrix_a, 16, 16, 8, wmma::precision::tf32, wmma::row_major> af[2];
#pragma unroll
            for (int i = 0; i < 2; i++) {
                wmma::load_matrix_sync(af[i], as + (wm * 32 + i * 16) * LDA_S + kk, LDA_S);
#pragma unroll
                for (int e = 0; e < af[i].num_elements; e++)
                    af[i].x[e] = wmma::__float_to_tf32(af[i].x[e]);
            }
            if (BLAY == 0) {
#pragma unroll
                for (int j = 0; j < NFR; j++) {
                    wmma::fragment<wmma::matrix_b, 16, 16, 8, wmma::precision::tf32, wmma::col_major> bf;
                    wmma::load_matrix_sync(bf, bs + (wn * WN + j * 16) * LDA_S + kk, LDA_S);
#pragma unroll
                    for (int e = 0; e < bf.num_elements; e++)
                        bf.x[e] = wmma::__float_to_tf32(bf.x[e]);
#pragma unroll
                    for (int i = 0; i < 2; i++)
                        wmma::mma_sync(acc[i][j], af[i], bf, acc[i][j]);
                }
            } else {
#pragma unroll
                for (int j = 0; j < NFR; j++) {
                    wmma::fragment<wmma::matrix_b, 16, 16, 8, wmma::precision::tf32, wmma::row_major> bf;
                    wmma::load_matrix_sync(bf, bs + kk * LDB_S + wn * WN + j * 16, LDB_S);
#pragma unroll
                    for (int e = 0; e < bf.num_elements; e++)
                        bf.x[e] = wmma::__float_to_tf32(bf.x[e]);
#pragma unroll
                    for (int i = 0; i < 2; i++)
                        wmma::mma_sync(acc[i][j], af[i], bf, acc[i][j]);
                }
            }
        }
        __syncthreads();
    }

    // ---- epilogue: stage through smem, then coalesced elementwise ----
    constexpr int LDC_S = BN + 4;
    float* Cs = smem;
#pragma unroll
    for (int i = 0; i < 2; i++)
#pragma unroll
        for (int j = 0; j < NFR; j++)
            wmma::store_matrix_sync(Cs + (wm * 32 + i * 16) * LDC_S + wn * WN + j * 16,
                                    acc[i][j], LDC_S, wmma::mem_row_major);
    __syncthreads();

#pragma unroll
    for (int i = 0; i < BM * BN / 4 / 256; i++) {
        int f4  = t + i * 256;
        int row = f4 / (BN / 4);
        int c4  = (f4 % (BN / 4)) * 4;
        float4 v = *(const float4*)(Cs + row * LDC_S + c4);
        int col = n0 + c4;
        if (EPI >= 1) {
            float4 bv = *(const float4*)(bias + col);
            v.x += bv.x; v.y += bv.y; v.z += bv.z; v.w += bv.w;
        }
        if (EPI == 2) {
            float* p = &v.x;
#pragma unroll
            for (int e = 0; e < 4; e++) {
                float u = p[e];
                p[e] = 0.5f * u * (1.f + tanhf(0.7978845608f * (u + 0.044715f * u * u * u)));
            }
        }
        if (EPI == 3) {
            float4 rv = *(const float4*)(res + (size_t)(m0 + row) * ldc + col);
            v.x += rv.x; v.y += rv.y; v.z += rv.z; v.w += rv.w;
        }
        *(float4*)(C + (size_t)(m0 + row) * ldc + col) = v;
    }
}

// ---------------- host launch ----------------
extern "C" void kernel_launch(void* const* d_in, const int* in_sizes, int n_in,
                              void* d_out, int out_size) {
    const float* x      = (const float*)d_in[0];
    const float* r      = (const float*)d_in[1];
    const float* ln1_g  = (const float*)d_in[2];
    const float* ln1_b  = (const float*)d_in[3];
    const float* qkv_w  = (const float*)d_in[4];
    const float* qkv_b  = (const float*)d_in[5];
    const float* conv_w = (const float*)d_in[6];
    const float* conv_b = (const float*)d_in[7];
    const float* proj_w = (const float*)d_in[8];
    const float* proj_b = (const float*)d_in[9];
    const float* ln2_g  = (const float*)d_in[10];
    const float* ln2_b  = (const float*)d_in[11];
    const float* fc1_w  = (const float*)d_in[12];
    const float* fc1_b  = (const float*)d_in[13];
    const float* fc2_w  = (const float*)d_in[14];
    const float* fc2_b  = (const float*)d_in[15];

    float* out    = (float*)d_out;
    float* out_x  = out;
    float* out_am = out + (size_t)ROWS * DIMC;
    float* out_un = out_am + (size_t)BC * HEADSC * NN;

    float *h_, *qkv_, *qk_, *av_, *x1_, *h2_, *fc1_;
    cudaGetSymbolAddress((void**)&h_,   g_h);
    cudaGetSymbolAddress((void**)&qkv_, g_qkv);
    cudaGetSymbolAddress((void**)&qk_,  g_qk);
    cudaGetSymbolAddress((void**)&av_,  g_av);
    cudaGetSymbolAddress((void**)&x1_,  g_x1);
    cudaGetSymbolAddress((void**)&h2_,  g_h2);
    cudaGetSymbolAddress((void**)&fc1_, g_fc1);

    // dynamic smem sizes
    const int SM_NT = (2 * (128 * LDA_S + 128 * LDA_S)) * 4;   // 73728 B
    const int SM_NN = (2 * (128 * LDA_S + BKC * (64 + 4))) * 4; // 54272 B

    cudaFuncSetAttribute((const void*)gemm_tc<128,0,0>, cudaFuncAttributeMaxDynamicSharedMemorySize, SM_NT);
    cudaFuncSetAttribute((const void*)gemm_tc<128,0,1>, cudaFuncAttributeMaxDynamicSharedMemorySize, SM_NT);
    cudaFuncSetAttribute((const void*)gemm_tc<128,0,2>, cudaFuncAttributeMaxDynamicSharedMemorySize, SM_NT);
    cudaFuncSetAttribute((const void*)gemm_tc<128,0,3>, cudaFuncAttributeMaxDynamicSharedMemorySize, SM_NT);
    cudaFuncSetAttribute((const void*)gemm_tc<64,1,0>,  cudaFuncAttributeMaxDynamicSharedMemorySize, SM_NN);

    // 1. ln1
    ln_kernel<<<ROWS, 256>>>(x, ln1_g, ln1_b, h_);

    // 2. qkv = h @ qkv_w^T + qkv_b
    gemm_tc<128,0,1><<<dim3(3 * DIMC / 128, ROWS / 128, 1), 256, SM_NT>>>(
        h_, qkv_w, qkv_, qkv_b, nullptr,
        DIMC, DIMC, DIMC, 3 * DIMC,
        0, 0, 0, 0, 0, 0, 1);

    // 3. qk[b,h] = Q @ K^T
    gemm_tc<128,0,0><<<dim3(NC / 128, NC / 128, BC * HEADSC), 256, SM_NT>>>(
        qkv_, qkv_ + DIMC, qk_, nullptr, nullptr,
        HDC, 3 * DIMC, 3 * DIMC, NC,
        (long)NC * 3 * DIMC, HDC,
        (long)NC * 3 * DIMC, HDC,
        (long)HEADSC * NN, (long)NN,
        HEADSC);

    // 4. softmax
    softmax_kernel<<<BC * HEADSC * NC, 256>>>(qk_, out_am);

    // 5. uncertainty + attn
    uncert_kernel<<<(BC * NN) / 256, 256>>>(r, conv_w, conv_b, qk_, out_am, out_un);

    // 6. av = attn @ V
    gemm_tc<64,1,0><<<dim3(1, NC / 128, BC * HEADSC), 256, SM_NN>>>(
        qk_, qkv_ + 2 * DIMC, av_, nullptr, nullptr,
        NC, NC, 3 * DIMC, DIMC,
        (long)HEADSC * NN, (long)NN,
        (long)NC * 3 * DIMC, HDC,
        (long)NC * DIMC, HDC,
        HEADSC);

    // 7. x1 = x + av @ proj_w^T + proj_b
    gemm_tc<128,0,3><<<dim3(DIMC / 128, ROWS / 128, 1), 256, SM_NT>>>(
        av_, proj_w, x1_, proj_b, x,
        DIMC, DIMC, DIMC, DIMC,
        0, 0, 0, 0, 0, 0, 1);

    // 8. ln2
    ln_kernel<<<ROWS, 256>>>(x1_, ln2_g, ln2_b, h2_);

    // 9. fc1 = gelu(h2 @ fc1_w^T + fc1_b)
    gemm_tc<128,0,2><<<dim3(MLPC / 128, ROWS / 128, 1), 256, SM_NT>>>(
        h2_, fc1_w, fc1_, fc1_b, nullptr,
        DIMC, DIMC, DIMC, MLPC,
        0, 0, 0, 0, 0, 0, 1);

    // 10. out_x = x1 + fc1 @ fc2_w^T + fc2_b
    gemm_tc<128,0,3><<<dim3(DIMC / 128, ROWS / 128, 1), 256, SM_NT>>>(
        fc1_, fc2_w, out_x, fc2_b, x1_,
        MLPC, MLPC, MLPC, DIMC,
        0, 0, 0, 0, 0, 0, 1);
}

// round 3
// speedup vs baseline: 3.8850x; 2.0290x over previous
#include <cuda_runtime.h>
#include <cuda_fp16.h>
#include <mma.h>
#include <math.h>

using namespace nvcuda;

#define DIMC   768
#define HEADSC 12
#define HDC    64
#define BC     2
#define NC     1024
#define MLPC   3072
#define ROWS   (BC * NC)
#define NN     (NC * NC)
#define SCALEC 0.125f

// ---------------- scratch ----------------
__device__ __half g_h   [ROWS * DIMC];             // ln1 out (half)
__device__ __half g_qkvh[ROWS * 3 * DIMC];         // qkv out (half)
__device__ float  g_qk  [(size_t)BC * HEADSC * NN];// raw scores fp32
__device__ __half g_attn[(size_t)BC * HEADSC * NN];// attn (half)
__device__ __half g_av  [ROWS * DIMC];             // attn@v (half)
__device__ float  g_x1  [ROWS * DIMC];             // x + proj (fp32)
__device__ __half g_h2  [ROWS * DIMC];             // ln2 out (half)
__device__ __half g_fc1 [ROWS * MLPC];             // gelu(fc1) (half)
__device__ __half g_wqkv[3 * DIMC * DIMC];
__device__ __half g_wpro[DIMC * DIMC];
__device__ __half g_wfc1[MLPC * DIMC];
__device__ __half g_wfc2[DIMC * MLPC];

// ---------------- fp32 -> fp16 ----------------
__global__ void f2h_kernel(const float* __restrict__ x, __half* __restrict__ y, int n) {
    int i = blockIdx.x * 1024 + threadIdx.x;
    if (i < n) y[i] = __float2half_rn(x[i]);
}

// ---------------- layernorm (half out) ----------------
__global__ void ln_kernel(const float* __restrict__ x, const float* __restrict__ g,
                          const float* __restrict__ b, __half* __restrict__ y) {
    int row = blockIdx.x;
    const float* xr = x + (size_t)row * DIMC;
    __half*      yr = y + (size_t)row * DIMC;
    float v[3];
    float s = 0.f, s2 = 0.f;
#pragma unroll
    for (int i = 0; i < 3; i++) {
        v[i] = xr[threadIdx.x + 256 * i];
        s += v[i]; s2 += v[i] * v[i];
    }
    __shared__ float sh[16];
#pragma unroll
    for (int o = 16; o; o >>= 1) {
        s  += __shfl_xor_sync(~0u, s,  o);
        s2 += __shfl_xor_sync(~0u, s2, o);
    }
    int w = threadIdx.x >> 5;
    if ((threadIdx.x & 31) == 0) { sh[w] = s; sh[8 + w] = s2; }
    __syncthreads();
    if (threadIdx.x < 32) {
        s  = threadIdx.x < 8 ? sh[threadIdx.x]     : 0.f;
        s2 = threadIdx.x < 8 ? sh[8 + threadIdx.x] : 0.f;
#pragma unroll
        for (int o = 4; o; o >>= 1) {
            s  += __shfl_xor_sync(~0u, s,  o);
            s2 += __shfl_xor_sync(~0u, s2, o);
        }
        if (threadIdx.x == 0) { sh[0] = s; sh[1] = s2; }
    }
    __syncthreads();
    float mean = sh[0] * (1.f / DIMC);
    float var  = sh[1] * (1.f / DIMC) - mean * mean;
    float rstd = rsqrtf(var + 1e-5f);
#pragma unroll
    for (int i = 0; i < 3; i++) {
        int c = threadIdx.x + 256 * i;
        yr[c] = __float2half_rn((v[i] - mean) * rstd * g[c] + b[c]);
    }
}

// ---------------- softmax ----------------
__global__ void softmax_kernel(const float* __restrict__ qk, float* __restrict__ am) {
    size_t base = (size_t)blockIdx.x * NC;
    float v[4];
    float m = -1e30f;
#pragma unroll
    for (int i = 0; i < 4; i++) {
        v[i] = qk[base + threadIdx.x + 256 * i] * SCALEC;
        m = fmaxf(m, v[i]);
    }
    __shared__ float sh[8];
#pragma unroll
    for (int o = 16; o; o >>= 1) m = fmaxf(m, __shfl_xor_sync(~0u, m, o));
    if ((threadIdx.x & 31) == 0) sh[threadIdx.x >> 5] = m;
    __syncthreads();
    if (threadIdx.x < 32) {
        m = threadIdx.x < 8 ? sh[threadIdx.x] : -1e30f;
#pragma unroll
        for (int o = 4; o; o >>= 1) m = fmaxf(m, __shfl_xor_sync(~0u, m, o));
        if (threadIdx.x == 0) sh[0] = m;
    }
    __syncthreads();
    m = sh[0];
    __syncthreads();
    float s = 0.f;
#pragma unroll
    for (int i = 0; i < 4; i++) { v[i] = __expf(v[i] - m); s += v[i]; }
#pragma unroll
    for (int o = 16; o; o >>= 1) s += __shfl_xor_sync(~0u, s, o);
    if ((threadIdx.x & 31) == 0) sh[threadIdx.x >> 5] = s;
    __syncthreads();
    if (threadIdx.x < 32) {
        s = threadIdx.x < 8 ? sh[threadIdx.x] : 0.f;
#pragma unroll
        for (int o = 4; o; o >>= 1) s += __shfl_xor_sync(~0u, s, o);
        if (threadIdx.x == 0) sh[0] = s;
    }
    __syncthreads();
    float inv = 1.f / sh[0];
#pragma unroll
    for (int i = 0; i < 4; i++)
        am[base + threadIdx.x + 256 * i] = v[i] * inv;
}

// -------- uncertainty; attn written as half --------
__global__ void uncert_kernel(const float* __restrict__ r, const float* __restrict__ cw,
                              const float* __restrict__ cb, const float* __restrict__ qk,
                              const float* __restrict__ am, float* __restrict__ unc,
                              __half* __restrict__ attn) {
    __shared__ float scw[HEADSC * HEADSC];
    __shared__ float scb[HEADSC];
    if (threadIdx.x < HEADSC * HEADSC) scw[threadIdx.x] = cw[threadIdx.x];
    if (threadIdx.x < HEADSC)          scb[threadIdx.x] = cb[threadIdx.x];
    __syncthreads();
    size_t idx = (size_t)blockIdx.x * 256 + threadIdx.x;
    int    bb  = (int)(idx >> 20);
    size_t nm  = idx & (size_t)(NN - 1);
    size_t base = ((size_t)bb * HEADSC << 20) + nm;
    float s[HEADSC];
#pragma unroll
    for (int h = 0; h < HEADSC; h++) s[h] = qk[base + ((size_t)h << 20)];
#pragma unroll
    for (int g = 0; g < HEADSC; g++) {
        float acc = scb[g];
#pragma unroll
        for (int h = 0; h < HEADSC; h++) acc += scw[g * HEADSC + h] * s[h];
        float u = 1.f / (1.f + __expf(-acc));
        size_t o = base + ((size_t)g << 20);
        unc[o]  = u;
        attn[o] = __float2half_rn(am[o] + u * r[o]);
    }
}

// ---------------- fp16 tensor-core GEMM ----------------
// C[M,N] = A[M,K] * op(B); BLAY=0: B is [N,K] (use B^T); BLAY=1: B is [K,N].
// BM=128, BK=32 (halves), 8 warps (4 M x 2 N), wmma m16n16k16, fp32 accum.
// EPI: 0 none, 1 +bias, 2 +bias+gelu, 3 +bias+residual(fp32)
// OUTH: 1 -> write half, 0 -> write fp32
#define BKC 32
#define LDA_S 40

__device__ __forceinline__ void cpa16h(__half* dst, const __half* src) {
    unsigned s = (unsigned)__cvta_generic_to_shared(dst);
    asm volatile("cp.async.cg.shared.global [%0], [%1], 16;" :: "r"(s), "l"(src));
}

template<int BN, int BLAY, int EPI, int OUTH>
__global__ __launch_bounds__(256)
void gemm_h(const __half* __restrict__ A, const __half* __restrict__ B,
            void* __restrict__ Cv, const float* __restrict__ bias,
            const float* __restrict__ res,
            int K, int lda, int ldb, int ldc,
            long sAb, long sAh, long sBb, long sBh, long sCb, long sCh,
            int Hdiv) {
    constexpr int BM  = 128;
    constexpr int WN  = BN / 2;
    constexpr int NFR = WN / 16;
    constexpr int ASZ = BM * LDA_S;                                   // halves
    constexpr int LDB_S = (BLAY == 0) ? LDA_S : (BN + 8);
    constexpr int BSZ = (BLAY == 0) ? BN * LDA_S : BKC * LDB_S;       // halves

    extern __shared__ __half smem[];
    __half* As[2] = { smem,       smem + ASZ + BSZ };
    __half* Bs[2] = { smem + ASZ, smem + 2 * ASZ + BSZ };

    int z  = blockIdx.z;
    int zb = z / Hdiv, zh = z % Hdiv;
    A += zb * sAb + zh * sAh;
    B += zb * sBb + zh * sBh;
    size_t coff = (size_t)zb * sCb + (size_t)zh * sCh;
    float*  Cf = (float*)Cv + coff;
    __half* Ch = (__half*)Cv + coff;
    if (EPI == 3) res += coff;

    int m0 = blockIdx.y * BM, n0 = blockIdx.x * BN;
    int t   = threadIdx.x;
    int wid = t >> 5;
    int wm  = wid & 3;
    int wn  = wid >> 2;

    wmma::fragment<wmma::accumulator, 16, 16, 16, float> acc[2][NFR];
#pragma unroll
    for (int i = 0; i < 2; i++)
#pragma unroll
        for (int j = 0; j < NFR; j++) wmma::fill_fragment(acc[i][j], 0.f);

    const int stages = K / BKC;

    auto load_tiles = [&](int k0, int st) {
#pragma unroll
        for (int i = 0; i < BM * BKC / 8 / 256; i++) {       // 2
            int f   = t + i * 256;
            int row = f >> 2;
            int c8  = (f & 3) * 8;
            cpa16h(As[st] + row * LDA_S + c8,
                   A + (size_t)(m0 + row) * lda + k0 + c8);
        }
        if (BLAY == 0) {
#pragma unroll
            for (int i = 0; i < BN * BKC / 8 / 256; i++) {
                int f   = t + i * 256;
                int row = f >> 2;
                int c8  = (f & 3) * 8;
                cpa16h(Bs[st] + row * LDA_S + c8,
                       B + (size_t)(n0 + row) * ldb + k0 + c8);
            }
        } else {
#pragma unroll
            for (int i = 0; i < BKC * BN / 8 / 256; i++) {
                int f   = t + i * 256;
                int row = f / (BN / 8);
                int c8  = (f % (BN / 8)) * 8;
                cpa16h(Bs[st] + row * LDB_S + c8,
                       B + (size_t)(k0 + row) * ldb + n0 + c8);
            }
        }
        asm volatile("cp.async.commit_group;" ::: "memory");
    };

    load_tiles(0, 0);

    for (int it = 0; it < stages; ++it) {
        int cur = it & 1;
        if (it + 1 < stages) {
            load_tiles((it + 1) * BKC, cur ^ 1);
            asm volatile("cp.async.wait_group 1;" ::: "memory");
        } else {
            asm volatile("cp.async.wait_group 0;" ::: "memory");
        }
        __syncthreads();

        const __half* as = As[cur];
        const __half* bs = Bs[cur];
#pragma unroll
        for (int kk = 0; kk < BKC; kk += 16) {
            wmma::fragment<wmma::matrix_a, 16, 16, 16, __half, wmma::row_major> af[2];
#pragma unroll
            for (int i = 0; i < 2; i++)
                wmma::load_matrix_sync(af[i], as + (wm * 32 + i * 16) * LDA_S + kk, LDA_S);
            if (BLAY == 0) {
#pragma unroll
                for (int j = 0; j < NFR; j++) {
                    wmma::fragment<wmma::matrix_b, 16, 16, 16, __half, wmma::col_major> bf;
                    wmma::load_matrix_sync(bf, bs + (wn * WN + j * 16) * LDA_S + kk, LDA_S);
#pragma unroll
                    for (int i = 0; i < 2; i++)
                        wmma::mma_sync(acc[i][j], af[i], bf, acc[i][j]);
                }
            } else {
#pragma unroll
                for (int j = 0; j < NFR; j++) {
                    wmma::fragment<wmma::matrix_b, 16, 16, 16, __half, wmma::row_major> bf;
                    wmma::load_matrix_sync(bf, bs + kk * LDB_S + wn * WN + j * 16, LDB_S);
#pragma unroll
                    for (int i = 0; i < 2; i++)
                        wmma::mma_sync(acc[i][j], af[i], bf, acc[i][j]);
                }
            }
        }
        __syncthreads();
    }

    if (EPI == 0 && OUTH == 0) {
        // direct fp32 store to global (qk GEMM — no per-element epilogue)
#pragma unroll
        for (int i = 0; i < 2; i++)
#pragma unroll
            for (int j = 0; j < NFR; j++)
                wmma::store_matrix_sync(
                    Cf + (size_t)(m0 + wm * 32 + i * 16) * ldc + n0 + wn * WN + j * 16,
                    acc[i][j], ldc, wmma::mem_row_major);
        return;
    }

    // stage through smem (fp32), then coalesced epilogue
    constexpr int LDC_S = BN + 4;
    float* Cs = (float*)smem;
#pragma unroll
    for (int i = 0; i < 2; i++)
#pragma unroll
        for (int j = 0; j < NFR; j++)
            wmma::store_matrix_sync(Cs + (wm * 32 + i * 16) * LDC_S + wn * WN + j * 16,
                                    acc[i][j], LDC_S, wmma::mem_row_major);
    __syncthreads();

#pragma unroll
    for (int i = 0; i < BM * BN / 4 / 256; i++) {
        int f4  = t + i * 256;
        int row = f4 / (BN / 4);
        int c4  = (f4 % (BN / 4)) * 4;
        float4 v = *(const float4*)(Cs + row * LDC_S + c4);
        int col = n0 + c4;
        if (EPI >= 1) {
            float4 bv = *(const float4*)(bias + col);
            v.x += bv.x; v.y += bv.y; v.z += bv.z; v.w += bv.w;
        }
        if (EPI == 2) {
            float* p = &v.x;
#pragma unroll
            for (int e = 0; e < 4; e++) {
                float u = p[e];
                p[e] = 0.5f * u * (1.f + tanhf(0.7978845608f * (u + 0.044715f * u * u * u)));
            }
        }
        if (EPI == 3) {
            float4 rv = *(const float4*)(res + (size_t)(m0 + row) * ldc + col);
            v.x += rv.x; v.y += rv.y; v.z += rv.z; v.w += rv.w;
        }
        if (OUTH) {
            __half2 h01 = __floats2half2_rn(v.x, v.y);
            __half2 h23 = __floats2half2_rn(v.z, v.w);
            __half2* dst = (__half2*)(Ch + (size_t)(m0 + row) * ldc + col);
            dst[0] = h01; dst[1] = h23;
        } else {
            *(float4*)(Cf + (size_t)(m0 + row) * ldc + col) = v;
        }
    }
}

// ---------------- host launch ----------------
extern "C" void kernel_launch(void* const* d_in, const int* in_sizes, int n_in,
                              void* d_out, int out_size) {
    const float* x      = (const float*)d_in[0];
    const float* r      = (const float*)d_in[1];
    const float* ln1_g  = (const float*)d_in[2];
    const float* ln1_b  = (const float*)d_in[3];
    const float* qkv_w  = (const float*)d_in[4];
    const float* qkv_b  = (const float*)d_in[5];
    const float* conv_w = (const float*)d_in[6];
    const float* conv_b = (const float*)d_in[7];
    const float* proj_w = (const float*)d_in[8];
    const float* proj_b = (const float*)d_in[9];
    const float* ln2_g  = (const float*)d_in[10];
    const float* ln2_b  = (const float*)d_in[11];
    const float* fc1_w  = (const float*)d_in[12];
    const float* fc1_b  = (const float*)d_in[13];
    const float* fc2_w  = (const float*)d_in[14];
    const float* fc2_b  = (const float*)d_in[15];

    float* out    = (float*)d_out;
    float* out_x  = out;
    float* out_am = out + (size_t)ROWS * DIMC;
    float* out_un = out_am + (size_t)BC * HEADSC * NN;

    __half *h_, *qkvh_, *attn_, *av_, *h2_, *fc1_, *wqkv_, *wpro_, *wfc1_, *wfc2_;
    float  *qk_, *x1_;
    cudaGetSymbolAddress((void**)&h_,    g_h);
    cudaGetSymbolAddress((void**)&qkvh_, g_qkvh);
    cudaGetSymbolAddress((void**)&qk_,   g_qk);
    cudaGetSymbolAddress((void**)&attn_, g_attn);
    cudaGetSymbolAddress((void**)&av_,   g_av);
    cudaGetSymbolAddress((void**)&x1_,   g_x1);
    cudaGetSymbolAddress((void**)&h2_,   g_h2);
    cudaGetSymbolAddress((void**)&fc1_,  g_fc1);
    cudaGetSymbolAddress((void**)&wqkv_, g_wqkv);
    cudaGetSymbolAddress((void**)&wpro_, g_wpro);
    cudaGetSymbolAddress((void**)&wfc1_, g_wfc1);
    cudaGetSymbolAddress((void**)&wfc2_, g_wfc2);

    // smem sizes (bytes)
    const int SM_MAIN_NT128 = 2 * (128 * LDA_S + 128 * LDA_S) * 2;       // 40960
    const int SM_EPI128     = 128 * (128 + 4) * 4;                       // 67584
    const int SM_NT128      = SM_EPI128;                                 // max
    const int SM_QK         = SM_MAIN_NT128;                             // direct store
    const int SM_NN64       = 128 * (64 + 4) * 4;                        // 34816 (> mainloop 29696)

    cudaFuncSetAttribute((const void*)gemm_h<128,0,1,1>, cudaFuncAttributeMaxDynamicSharedMemorySize, SM_NT128);
    cudaFuncSetAttribute((const void*)gemm_h<128,0,0,0>, cudaFuncAttributeMaxDynamicSharedMemorySize, SM_QK);
    cudaFuncSetAttribute((const void*)gemm_h<64,1,0,1>,  cudaFuncAttributeMaxDynamicSharedMemorySize, SM_NN64);
    cudaFuncSetAttribute((const void*)gemm_h<128,0,3,0>, cudaFuncAttributeMaxDynamicSharedMemorySize, SM_NT128);
    cudaFuncSetAttribute((const void*)gemm_h<128,0,2,1>, cudaFuncAttributeMaxDynamicSharedMemorySize, SM_NT128);

    // 0. weight conversion (fp32 -> fp16)
    f2h_kernel<<<(3 * DIMC * DIMC + 1023) / 1024, 1024>>>(qkv_w, wqkv_, 3 * DIMC * DIMC);
    f2h_kernel<<<(DIMC * DIMC + 1023) / 1024, 1024>>>(proj_w, wpro_, DIMC * DIMC);
    f2h_kernel<<<(MLPC * DIMC + 1023) / 1024, 1024>>>(fc1_w, wfc1_, MLPC * DIMC);
    f2h_kernel<<<(DIMC * MLPC + 1023) / 1024, 1024>>>(fc2_w, wfc2_, DIMC * MLPC);

    // 1. ln1 (half out)
    ln_kernel<<<ROWS, 256>>>(x, ln1_g, ln1_b, h_);

    // 2. qkv = h @ qkv_w^T + qkv_b  -> half
    gemm_h<128,0,1,1><<<dim3(3 * DIMC / 128, ROWS / 128, 1), 256, SM_NT128>>>(
        h_, wqkv_, qkvh_, qkv_b, nullptr,
        DIMC, DIMC, DIMC, 3 * DIMC,
        0, 0, 0, 0, 0, 0, 1);

    // 3. qk = Q @ K^T -> fp32 raw scores (direct store)
    gemm_h<128,0,0,0><<<dim3(NC / 128, NC / 128, BC * HEADSC), 256, SM_QK>>>(
        qkvh_, qkvh_ + DIMC, qk_, nullptr, nullptr,
        HDC, 3 * DIMC, 3 * DIMC, NC,
        (long)NC * 3 * DIMC, HDC,
        (long)NC * 3 * DIMC, HDC,
        (long)HEADSC * NN, (long)NN,
        HEADSC);

    // 4. softmax -> out_am (fp32)
    softmax_kernel<<<BC * HEADSC * NC, 256>>>(qk_, out_am);

    // 5. uncertainty (fp32 out) + attn (half)
    uncert_kernel<<<(BC * NN) / 256, 256>>>(r, conv_w, conv_b, qk_, out_am, out_un, attn_);

    // 6. av = attn @ V -> half
    gemm_h<64,1,0,1><<<dim3(1, NC / 128, BC * HEADSC), 256, SM_NN64>>>(
        attn_, qkvh_ + 2 * DIMC, av_, nullptr, nullptr,
        NC, NC, 3 * DIMC, DIMC,
        (long)HEADSC * NN, (long)NN,
        (long)NC * 3 * DIMC, HDC,
        (long)NC * DIMC, HDC,
        HEADSC);

    // 7. x1 = x + av @ proj_w^T + proj_b -> fp32
    gemm_h<128,0,3,0><<<dim3(DIMC / 128, ROWS / 128, 1), 256, SM_NT128>>>(
        av_, wpro_, x1_, proj_b, x,
        DIMC, DIMC, DIMC, DIMC,
        0, 0, 0, 0, 0, 0, 1);

    // 8. ln2 (half out)
    ln_kernel<<<ROWS, 256>>>(x1_, ln2_g, ln2_b, h2_);

    // 9. fc1 = gelu(h2 @ fc1_w^T + fc1_b) -> half
    gemm_h<128,0,2,1><<<dim3(MLPC / 128, ROWS / 128, 1), 256, SM_NT128>>>(
        h2_, wfc1_, fc1_, fc1_b, nullptr,
        DIMC, DIMC, DIMC, MLPC,
        0, 0, 0, 0, 0, 0, 1);

    // 10. out_x = x1 + fc1 @ fc2_w^T + fc2_b -> fp32
    gemm_h<128,0,3,0><<<dim3(DIMC / 128, ROWS / 128, 1), 256, SM_NT128>>>(
        fc1_, wfc2_, out_x, fc2_b, x1_,
        MLPC, MLPC, MLPC, DIMC,
        0, 0, 0, 0, 0, 0, 1);
}